// round 16
// baseline (speedup 1.0000x reference)
#include <cuda_runtime.h>
#include <cuda_bf16.h>
#include <mma.h>

using namespace nvcuda;

// Problem dims
#define BB 64
#define TT 512
#define DD 1024
#define HH 1024
#define G3 3072   // 3*H gates
#define NBLK 96   // persistent blocks (3 parts x 32 j-slices of width 32)

// ---------------- device scratch (static, allowed) ----------------
// W order: 0=Wx0, 1=Wh0, 2=Wx1, 3=Wh1  (each [3072,1024], row-major)
__device__ __nv_bfloat16 g_Whi[4][G3 * HH];
__device__ __nv_bfloat16 g_Wlo[4][G3 * HH];
__device__ __nv_bfloat16 g_xhi[BB * TT * DD];
__device__ __nv_bfloat16 g_xlo[BB * TT * DD];
__device__ float g_GX0[TT * BB * G3];          // precomputed x-projection, layer 0 (no bias)
__device__ float g_gx1[2][BB * G3];            // layer1 x-side scratch (no bias)
__device__ __nv_bfloat16 g_h0hi[2][BB * HH];
__device__ __nv_bfloat16 g_h0lo[2][BB * HH];
__device__ __nv_bfloat16 g_h1hi[2][BB * HH];
__device__ __nv_bfloat16 g_h1lo[2][BB * HH];

// grid barrier state (reset by setup kernel every launch)
__device__ unsigned g_arrive;
__device__ unsigned g_release;

// ---------------- cp.async helpers ----------------
#define CP_ASYNC16(dst_u32, src_ptr) \
    asm volatile("cp.async.cg.shared.global [%0], [%1], 16;\n" :: "r"(dst_u32), "l"(src_ptr))
#define CP_COMMIT() asm volatile("cp.async.commit_group;\n" ::: "memory")
#define CP_WAIT0()  asm volatile("cp.async.wait_group 0;\n" ::: "memory")

// ---------------- fast gate functions (MUFU-based) ----------------
__device__ __forceinline__ float fsig(float x)  { return 1.0f / (1.0f + __expf(-x)); }
__device__ __forceinline__ float ftanh(float x) { return 2.0f / (1.0f + __expf(-2.0f * x)) - 1.0f; }

// ---------------- fused setup: all splits + state init + barrier reset ----------------
__global__ void setup_kernel(const float* __restrict__ Wx0, const float* __restrict__ Wh0,
                             const float* __restrict__ Wx1, const float* __restrict__ Wh1,
                             const float* __restrict__ x) {
    const long i0 = (long)blockIdx.x * blockDim.x + threadIdx.x;
    const long stride = (long)gridDim.x * blockDim.x;
    const long nW = (long)G3 * HH;

    // weights (4 matrices)
    for (long i = i0; i < 4 * nW; i += stride) {
        int w = (int)(i / nW);
        long k = i - (long)w * nW;
        const float* src = (w == 0) ? Wx0 : (w == 1) ? Wh0 : (w == 2) ? Wx1 : Wh1;
        float v = src[k];
        __nv_bfloat16 h = __float2bfloat16(v);
        g_Whi[w][k] = h;
        g_Wlo[w][k] = __float2bfloat16(v - __bfloat162float(h));
    }
    // x
    const long nX = (long)BB * TT * DD;
    for (long i = i0; i < nX; i += stride) {
        float v = x[i];
        __nv_bfloat16 h = __float2bfloat16(v);
        g_xhi[i] = h;
        g_xlo[i] = __float2bfloat16(v - __bfloat162float(h));
    }
    // hidden states (both ping-pong slots)
    const __nv_bfloat16 z = __float2bfloat16(0.0f);
    for (long i = i0; i < 2L * BB * HH; i += stride) {
        ((__nv_bfloat16*)g_h0hi)[i] = z;
        ((__nv_bfloat16*)g_h0lo)[i] = z;
        ((__nv_bfloat16*)g_h1hi)[i] = z;
        ((__nv_bfloat16*)g_h1lo)[i] = z;
    }
    if (i0 == 0) { g_arrive = 0; g_release = 0; }
}

// ---------------- pad: aligns recur_kernel at process launch #5 for ncu ----------------
__global__ void pad_kernel() {}

// ---------------- Phase A: GX0[(t,b), n] = x @ Wx0^T (no bias) ----------------
__global__ void __launch_bounds__(256) phaseA_kernel() {
    __shared__ __align__(32) __nv_bfloat16 As_hi[128][40];
    __shared__ __align__(32) __nv_bfloat16 As_lo[128][40];

    const int tid = threadIdx.x;
    const int wid = tid >> 5;
    const int n_w = blockIdx.x * 128 + wid * 16;
    const int m0  = blockIdx.y * 128;

    wmma::fragment<wmma::accumulator, 16, 16, 16, float> acc[8];
#pragma unroll
    for (int i = 0; i < 8; i++) wmma::fill_fragment(acc[i], 0.0f);

    const __nv_bfloat162* xh2 = (const __nv_bfloat162*)g_xhi;
    const __nv_bfloat162* xl2 = (const __nv_bfloat162*)g_xlo;

    for (int kc = 0; kc < 1024; kc += 32) {
        __syncthreads();
        for (int l = tid; l < 128 * 16; l += 256) {
            int r  = l >> 4;
            int c2 = l & 15;
            int rg = m0 + r;
            int t = rg >> 6;
            int b = rg & 63;
            int off = ((b * TT + t) * DD + kc) / 2 + c2;
            ((__nv_bfloat162*)&As_hi[r][0])[c2] = xh2[off];
            ((__nv_bfloat162*)&As_lo[r][0])[c2] = xl2[off];
        }
        __syncthreads();
#pragma unroll
        for (int kk = 0; kk < 32; kk += 16) {
            wmma::fragment<wmma::matrix_b, 16, 16, 16, __nv_bfloat16, wmma::col_major> bhi, blo;
            wmma::load_matrix_sync(bhi, g_Whi[0] + (size_t)n_w * 1024 + kc + kk, 1024);
            wmma::load_matrix_sync(blo, g_Wlo[0] + (size_t)n_w * 1024 + kc + kk, 1024);
#pragma unroll
            for (int i = 0; i < 8; i++) {
                wmma::fragment<wmma::matrix_a, 16, 16, 16, __nv_bfloat16, wmma::row_major> ahi, alo;
                wmma::load_matrix_sync(ahi, &As_hi[16 * i][kk], 40);
                wmma::load_matrix_sync(alo, &As_lo[16 * i][kk], 40);
                wmma::mma_sync(acc[i], ahi, bhi, acc[i]);
                wmma::mma_sync(acc[i], ahi, blo, acc[i]);
                wmma::mma_sync(acc[i], alo, bhi, acc[i]);
            }
        }
    }
#pragma unroll
    for (int i = 0; i < 8; i++) {
        int rg = m0 + 16 * i;
        int t  = rg >> 6;
        int b0 = rg & 63;
        float* dst = g_GX0 + (size_t)(t * BB + b0) * G3 + n_w;
        wmma::store_matrix_sync(dst, acc[i], G3, wmma::mem_row_major);
    }
}

// ---------------- grid barrier ----------------
__device__ __forceinline__ void gsync(unsigned r) {
    __syncthreads();
    if (threadIdx.x == 0) {
        __threadfence();
        unsigned a = atomicAdd(&g_arrive, 1u);
        if (a == r * NBLK - 1u) {
            atomicExch(&g_release, r);
        } else {
            volatile unsigned* rel = &g_release;
            while (*rel < r) { }
        }
        __threadfence();
    }
    __syncthreads();
}

// ---------------- persistent recurrence kernel ----------------
// 96 blocks x 256 threads. block = (part, j0): part = bx/32, j0 = (bx%32)*32.
//  part 0: layer0 step t=p   : gh0 = h0(t-1)@Wh0^T, combine -> h0(t)
//  part 1: layer1 x  t=p-1   : gx1 = h0(t)@Wx1^T -> scratch
//  part 2: layer1 h  t=p-2   : gh1 = h1(t-1)@Wh1^T, combine -> h1(t)
// W_hi tile (96 x 1024 bf16) SMEM-stationary for the whole kernel.
// Per-chunk (K=32) staging of A(hi|lo packed) + W_lo via cp.async, double-buffered.
#define WHI_LD 1032              // 1024 + 8 pad
#define AS_LD 72                 // packed row: hi[0..31] | lo[32..63] | pad (144B, 16B-aligned)
#define BLO_LD 40                // 32 + 8 pad (80B rows, 16B-aligned)
#define SACC_LD 36               // 32 + 4 pad (float)
#define KCH 32                   // K per chunk
#define NCH 32                   // chunks per phase
#define SMEM_WHI_BYTES (96 * WHI_LD * 2)            // 198144
#define STAGE_BUF_ELEMS (64 * AS_LD + 96 * BLO_LD)  // 4608 + 3840 = 8448 bf16
#define STAGE_BUF_BYTES (STAGE_BUF_ELEMS * 2)       // 16896
// union region: 2 staging buffers (33792) vs sacc (3*64*36*4 = 27648) -> 33792
#define SMEM_UNION_BYTES (2 * STAGE_BUF_BYTES)
#define SMEM_TOTAL_BYTES (SMEM_WHI_BYTES + SMEM_UNION_BYTES)  // 231936

__global__ void __launch_bounds__(256) recur_kernel(
    const float* __restrict__ bx0, const float* __restrict__ bh0,
    const float* __restrict__ bx1, const float* __restrict__ bh1)
{
    extern __shared__ __align__(16) unsigned char s_raw[];
    __nv_bfloat16* Whi_s = (__nv_bfloat16*)s_raw;
    __nv_bfloat16* stage0 = (__nv_bfloat16*)(s_raw + SMEM_WHI_BYTES);
    float*         saccf  = (float*)(s_raw + SMEM_WHI_BYTES);   // union with staging

    const int tid  = threadIdx.x;
    const int wid  = tid >> 5;
    const int part = blockIdx.x >> 5;           // 0..2
    const int j0   = (blockIdx.x & 31) * 32;    // hidden slice base
    const int ms   = wid >> 1;                  // A row slice (0..3)
    const int nf   = wid & 1;                   // n sub-frag (0..1)

    const int widx = part + 1;                  // W matrix: 1=Wh0, 2=Wx1, 3=Wh1

    // ---- load this block's W_hi tile into SMEM (once per launch) ----
    {
        const uint4* src = (const uint4*)(g_Whi[widx]);
        for (int l = tid; l < 96 * 128; l += 256) {
            int r = l >> 7, c = l & 127;
            int grow = (r >> 5) * 1024 + j0 + (r & 31);
            *(uint4*)&Whi_s[r * WHI_LD + c * 8] = src[grow * 128 + c];
        }
    }
    __syncthreads();

    const uint4* wlo_src = (const uint4*)(g_Wlo[widx]);
    const float* bx = (part == 0) ? bx0 : bx1;
    const float* bh = (part == 0) ? bh0 : bh1;

    const unsigned stage_u32 = (unsigned)__cvta_generic_to_shared(stage0);

    for (int p = 0; p < 514; ++p) {
        int t;
        bool valid;
        if (part == 0)      { t = p;     valid = (t <= 511); }
        else if (part == 1) { t = p - 1; valid = (t >= 0 && t <= 511); }
        else                { t = p - 2; valid = (t >= 0 && t <= 511); }

        if (valid) {
            const __nv_bfloat16 *Ahi, *Alo;
            if (part == 0)      { Ahi = g_h0hi[(t + 1) & 1]; Alo = g_h0lo[(t + 1) & 1]; }
            else if (part == 1) { Ahi = g_h0hi[t & 1];       Alo = g_h0lo[t & 1]; }
            else                { Ahi = g_h1hi[(t + 1) & 1]; Alo = g_h1lo[(t + 1) & 1]; }

            const uint4* a_hi4 = (const uint4*)Ahi;
            const uint4* a_lo4 = (const uint4*)Alo;

            wmma::fragment<wmma::accumulator, 16, 16, 16, float> acc[3];
#pragma unroll
            for (int g = 0; g < 3; g++) wmma::fill_fragment(acc[g], 0.0f);

            // ---- staging lambda: chunk c into buffer (c&1) ----
            auto stage = [&](int c) {
                const int kq = c * (KCH / 8);                 // uint4 offset in 128-uint4 row
                const unsigned buf = stage_u32 + (unsigned)((c & 1) * STAGE_BUF_BYTES);
                // A: 512 x 16B copies -> 2 per thread
#pragma unroll
                for (int i = 0; i < 2; i++) {
                    int l = tid + i * 256;
                    int r = l >> 3;          // 0..63
                    int s = l & 7;           // 0..7
                    const uint4* sp = (s < 4) ? (a_hi4 + r * 128 + kq + s)
                                              : (a_lo4 + r * 128 + kq + (s - 4));
                    int col = (s < 4) ? (s * 8) : (32 + (s - 4) * 8);
                    unsigned d = buf + (unsigned)((r * AS_LD + col) * 2);
                    CP_ASYNC16(d, (const void*)sp);
                }
                // Wlo: 384 copies (96 rows x 4 x 16B)
                {
                    int l = tid;
                    {
                        int r = l >> 2, q = l & 3;
                        int grow = (r >> 5) * 1024 + j0 + (r & 31);
                        unsigned d = buf + (unsigned)((64 * AS_LD + r * BLO_LD + q * 8) * 2);
                        CP_ASYNC16(d, (const void*)(wlo_src + grow * 128 + kq + q));
                    }
                    if (l < 128) {
                        l += 256;
                        int r = l >> 2, q = l & 3;
                        int grow = (r >> 5) * 1024 + j0 + (r & 31);
                        unsigned d = buf + (unsigned)((64 * AS_LD + r * BLO_LD + q * 8) * 2);
                        CP_ASYNC16(d, (const void*)(wlo_src + grow * 128 + kq + q));
                    }
                }
                CP_COMMIT();
            };

            stage(0);

            for (int c = 0; c < NCH; ++c) {
                CP_WAIT0();          // chunk c landed (this thread's copies)
                __syncthreads();     // visible to all; all warps done with other buffer
                if (c + 1 < NCH) stage(c + 1);   // async fill of other buffer

                const __nv_bfloat16* As  = stage0 + (c & 1) * STAGE_BUF_ELEMS;
                const __nv_bfloat16* Bls = As + 64 * AS_LD;
#pragma unroll
                for (int kk = 0; kk < KCH; kk += 16) {
                    wmma::fragment<wmma::matrix_a, 16, 16, 16, __nv_bfloat16, wmma::row_major> ahi, alo;
                    wmma::load_matrix_sync(ahi, As + ms * 16 * AS_LD + kk, AS_LD);
                    wmma::load_matrix_sync(alo, As + ms * 16 * AS_LD + 32 + kk, AS_LD);
#pragma unroll
                    for (int g = 0; g < 3; g++) {
                        wmma::fragment<wmma::matrix_b, 16, 16, 16, __nv_bfloat16, wmma::col_major> bhi, blo;
                        wmma::load_matrix_sync(bhi, &Whi_s[(g * 32 + nf * 16) * WHI_LD + c * KCH + kk], WHI_LD);
                        wmma::load_matrix_sync(blo, Bls + (g * 32 + nf * 16) * BLO_LD + kk, BLO_LD);
                        wmma::mma_sync(acc[g], ahi, bhi, acc[g]);
                        wmma::mma_sync(acc[g], ahi, blo, acc[g]);
                        wmma::mma_sync(acc[g], alo, bhi, acc[g]);
                    }
                }
            }
            __syncthreads();   // all warps done reading staging -> safe to write sacc (union)
#pragma unroll
            for (int g = 0; g < 3; g++)
                wmma::store_matrix_sync(saccf + (g * 64 + ms * 16) * SACC_LD + nf * 16,
                                        acc[g], SACC_LD, wmma::mem_row_major);
            __syncthreads();

            if (part == 1) {
                float* dst = g_gx1[t & 1];
                for (int l = tid; l < 64 * 32; l += 256) {
                    int b = l >> 5, jj = l & 31;
                    int j = j0 + jj;
                    dst[b * G3 + j]        = saccf[(0 * 64 + b) * SACC_LD + jj];
                    dst[b * G3 + 1024 + j] = saccf[(1 * 64 + b) * SACC_LD + jj];
                    dst[b * G3 + 2048 + j] = saccf[(2 * 64 + b) * SACC_LD + jj];
                }
            } else {
                __nv_bfloat16* outhi = (part == 0) ? g_h0hi[t & 1] : g_h1hi[t & 1];
                __nv_bfloat16* outlo = (part == 0) ? g_h0lo[t & 1] : g_h1lo[t & 1];
                for (int l = tid; l < 64 * 32; l += 256) {
                    int b = l >> 5, jj = l & 31;
                    int j = j0 + jj;
                    float ir, iz, in_;
                    if (part == 0) {
                        const float* gxr = g_GX0 + (size_t)(t * BB + b) * G3;
                        ir  = gxr[j]        + bx[j];
                        iz  = gxr[1024 + j] + bx[1024 + j];
                        in_ = gxr[2048 + j] + bx[2048 + j];
                    } else {
                        const float* gxr = g_gx1[t & 1] + b * G3;
                        ir  = gxr[j]        + bx[j];
                        iz  = gxr[1024 + j] + bx[1024 + j];
                        in_ = gxr[2048 + j] + bx[2048 + j];
                    }
                    float hr = saccf[(0 * 64 + b) * SACC_LD + jj] + bh[j];
                    float hz = saccf[(1 * 64 + b) * SACC_LD + jj] + bh[1024 + j];
                    float hn = saccf[(2 * 64 + b) * SACC_LD + jj] + bh[2048 + j];

                    float r = fsig(ir + hr);
                    float z = fsig(iz + hz);
                    float n = ftanh(in_ + r * hn);
                    float hp = __bfloat162float(Ahi[b * HH + j]) + __bfloat162float(Alo[b * HH + j]);
                    float hnew = n + z * (hp - n);

                    __nv_bfloat16 hh = __float2bfloat16(hnew);
                    outhi[b * HH + j] = hh;
                    outlo[b * HH + j] = __float2bfloat16(hnew - __bfloat162float(hh));
                }
            }
        }

        gsync((unsigned)(p + 1));
    }
}

// ---------------- FC: out[b] = h1(511)[b,:] . fcW + fcb ----------------
__global__ void fc_kernel(const float* __restrict__ fcW, const float* __restrict__ fcb,
                          float* __restrict__ out) {
    const int b = blockIdx.x;
    const int tid = threadIdx.x;
    const __nv_bfloat16* hh = g_h1hi[1] + b * HH;   // t=511 -> buffer 1
    const __nv_bfloat16* hl = g_h1lo[1] + b * HH;
    float s = 0.0f;
    for (int k = tid; k < HH; k += 128)
        s += (__bfloat162float(hh[k]) + __bfloat162float(hl[k])) * fcW[k];
    __shared__ float red[128];
    red[tid] = s;
    __syncthreads();
    for (int o = 64; o > 0; o >>= 1) {
        if (tid < o) red[tid] += red[tid + o];
        __syncthreads();
    }
    if (tid == 0) out[b] = red[0] + fcb[0];
}

// ---------------- host ----------------
extern "C" void kernel_launch(void* const* d_in, const int* in_sizes, int n_in,
                              void* d_out, int out_size) {
    const float* x   = (const float*)d_in[0];
    const float* Wx0 = (const float*)d_in[1];
    const float* bx0 = (const float*)d_in[2];
    const float* Wh0 = (const float*)d_in[3];
    const float* bh0 = (const float*)d_in[4];
    const float* Wx1 = (const float*)d_in[5];
    const float* bx1 = (const float*)d_in[6];
    const float* Wh1 = (const float*)d_in[7];
    const float* bh1 = (const float*)d_in[8];
    const float* fcW = (const float*)d_in[9];
    const float* fcb = (const float*)d_in[10];
    float* out = (float*)d_out;

    static int smem_set = 0;
    if (!smem_set) {
        cudaFuncSetAttribute(recur_kernel, cudaFuncAttributeMaxDynamicSharedMemorySize,
                             SMEM_TOTAL_BYTES);
        smem_set = 1;
    }

    // launch #0: fused splits + state init + barrier reset
    setup_kernel<<<4096, 256>>>(Wx0, Wh0, Wx1, Wh1, x);

    // launch #1: parallel x-projection for layer 0
    {
        dim3 grid(G3 / 128, (TT * BB) / 128);   // (24, 256)
        phaseA_kernel<<<grid, 256>>>();
    }

    // launch #2: pad (aligns recur at process launch #5 for ncu -s 5)
    pad_kernel<<<1, 32>>>();

    // launch #3: persistent pipelined recurrence: 514 phases, one kernel
    recur_kernel<<<NBLK, 256, SMEM_TOTAL_BYTES>>>(bx0, bh0, bx1, bh1);

    // launch #4: final FC
    fc_kernel<<<BB, 128>>>(fcW, fcb, out);

    (void)in_sizes; (void)n_in; (void)out_size;
}

// round 17
// speedup vs baseline: 1.5239x; 1.5239x over previous
#include <cuda_runtime.h>
#include <cuda_bf16.h>
#include <mma.h>

using namespace nvcuda;

// Problem dims
#define BB 64
#define TT 512
#define DD 1024
#define HH 1024
#define G3 3072   // 3*H gates
#define NBLK 96   // persistent blocks: 3 parts x 32 j-slices (width 32)
#define PBLK 32   // blocks per part
#define NTHR 384  // 12 warps

// ---------------- device scratch (static, allowed) ----------------
__device__ __nv_bfloat16 g_Whi[4][G3 * HH];
__device__ __nv_bfloat16 g_Wlo[4][G3 * HH];
__device__ __nv_bfloat16 g_xhi[BB * TT * DD];
__device__ __nv_bfloat16 g_xlo[BB * TT * DD];
__device__ float g_GX0[TT * BB * G3];
__device__ float g_gx1[2][BB * G3];
__device__ __nv_bfloat16 g_h0hi[2][BB * HH];
__device__ __nv_bfloat16 g_h0lo[2][BB * HH];
__device__ __nv_bfloat16 g_h1hi[2][BB * HH];
__device__ __nv_bfloat16 g_h1lo[2][BB * HH];

// per-part completion counters (cacheline-separated), reset each launch
struct __align__(128) PadCnt { unsigned v; unsigned pad[31]; };
__device__ PadCnt g_cnt[3];

// ---------------- cp.async helpers ----------------
#define CP_ASYNC16(dst_u32, src_ptr) \
    asm volatile("cp.async.cg.shared.global [%0], [%1], 16;\n" :: "r"(dst_u32), "l"(src_ptr))
#define CP_COMMIT() asm volatile("cp.async.commit_group;\n" ::: "memory")
#define CP_WAIT0()  asm volatile("cp.async.wait_group 0;\n" ::: "memory")

// ---------------- fast gates + L2 loads ----------------
__device__ __forceinline__ float fsig(float x)  { return 1.0f / (1.0f + __expf(-x)); }
__device__ __forceinline__ float ftanh(float x) { return 2.0f / (1.0f + __expf(-2.0f * x)) - 1.0f; }
__device__ __forceinline__ float ld_bf16_cg(const __nv_bfloat16* p) {
    unsigned short u = __ldcg((const unsigned short*)p);
    __nv_bfloat16_raw r; r.x = u;
    return __bfloat162float(__nv_bfloat16(r));
}

// ---------------- fused setup ----------------
__global__ void setup_kernel(const float* __restrict__ Wx0, const float* __restrict__ Wh0,
                             const float* __restrict__ Wx1, const float* __restrict__ Wh1,
                             const float* __restrict__ x) {
    const long i0 = (long)blockIdx.x * blockDim.x + threadIdx.x;
    const long stride = (long)gridDim.x * blockDim.x;
    const long nW = (long)G3 * HH;

    for (long i = i0; i < 4 * nW; i += stride) {
        int w = (int)(i / nW);
        long k = i - (long)w * nW;
        const float* src = (w == 0) ? Wx0 : (w == 1) ? Wh0 : (w == 2) ? Wx1 : Wh1;
        float v = src[k];
        __nv_bfloat16 h = __float2bfloat16(v);
        g_Whi[w][k] = h;
        g_Wlo[w][k] = __float2bfloat16(v - __bfloat162float(h));
    }
    const long nX = (long)BB * TT * DD;
    for (long i = i0; i < nX; i += stride) {
        float v = x[i];
        __nv_bfloat16 h = __float2bfloat16(v);
        g_xhi[i] = h;
        g_xlo[i] = __float2bfloat16(v - __bfloat162float(h));
    }
    const __nv_bfloat16 z = __float2bfloat16(0.0f);
    for (long i = i0; i < 2L * BB * HH; i += stride) {
        ((__nv_bfloat16*)g_h0hi)[i] = z;
        ((__nv_bfloat16*)g_h0lo)[i] = z;
        ((__nv_bfloat16*)g_h1hi)[i] = z;
        ((__nv_bfloat16*)g_h1lo)[i] = z;
    }
    if (i0 < 3) g_cnt[i0].v = 0;
}

// ---------------- pad: keeps recur_kernel at process launch #5 for ncu ----------------
__global__ void pad_kernel() {}

// ---------------- Phase A: GX0[(t,b), n] = x @ Wx0^T (no bias) ----------------
__global__ void __launch_bounds__(256) phaseA_kernel() {
    __shared__ __align__(32) __nv_bfloat16 As_hi[128][40];
    __shared__ __align__(32) __nv_bfloat16 As_lo[128][40];

    const int tid = threadIdx.x;
    const int wid = tid >> 5;
    const int n_w = blockIdx.x * 128 + wid * 16;
    const int m0  = blockIdx.y * 128;

    wmma::fragment<wmma::accumulator, 16, 16, 16, float> acc[8];
#pragma unroll
    for (int i = 0; i < 8; i++) wmma::fill_fragment(acc[i], 0.0f);

    const __nv_bfloat162* xh2 = (const __nv_bfloat162*)g_xhi;
    const __nv_bfloat162* xl2 = (const __nv_bfloat162*)g_xlo;

    for (int kc = 0; kc < 1024; kc += 32) {
        __syncthreads();
        for (int l = tid; l < 128 * 16; l += 256) {
            int r  = l >> 4;
            int c2 = l & 15;
            int rg = m0 + r;
            int t = rg >> 6;
            int b = rg & 63;
            int off = ((b * TT + t) * DD + kc) / 2 + c2;
            ((__nv_bfloat162*)&As_hi[r][0])[c2] = xh2[off];
            ((__nv_bfloat162*)&As_lo[r][0])[c2] = xl2[off];
        }
        __syncthreads();
#pragma unroll
        for (int kk = 0; kk < 32; kk += 16) {
            wmma::fragment<wmma::matrix_b, 16, 16, 16, __nv_bfloat16, wmma::col_major> bhi, blo;
            wmma::load_matrix_sync(bhi, g_Whi[0] + (size_t)n_w * 1024 + kc + kk, 1024);
            wmma::load_matrix_sync(blo, g_Wlo[0] + (size_t)n_w * 1024 + kc + kk, 1024);
#pragma unroll
            for (int i = 0; i < 8; i++) {
                wmma::fragment<wmma::matrix_a, 16, 16, 16, __nv_bfloat16, wmma::row_major> ahi, alo;
                wmma::load_matrix_sync(ahi, &As_hi[16 * i][kk], 40);
                wmma::load_matrix_sync(alo, &As_lo[16 * i][kk], 40);
                wmma::mma_sync(acc[i], ahi, bhi, acc[i]);
                wmma::mma_sync(acc[i], ahi, blo, acc[i]);
                wmma::mma_sync(acc[i], alo, bhi, acc[i]);
            }
        }
    }
#pragma unroll
    for (int i = 0; i < 8; i++) {
        int rg = m0 + 16 * i;
        int t  = rg >> 6;
        int b0 = rg & 63;
        float* dst = g_GX0 + (size_t)(t * BB + b0) * G3 + n_w;
        wmma::store_matrix_sync(dst, acc[i], G3, wmma::mem_row_major);
    }
}

// ---------------- persistent recurrence kernel (decoupled 3-stage pipeline) ----------------
// 96 blocks x 384 threads. part = bx>>5 (0..2), j0 = (bx&31)*32.
//  part 0, step t: gh0 = h0(t-1)@Wh0^T + combine -> h0(t)         [t = 0..511]
//  part 1, step t: gx1(t) = h0(t)@Wx1^T -> scratch                [t = 0..511]
//  part 2, step t: gh1 = h1(t-1)@Wh1^T + combine(gx1(t)) -> h1(t) [t = 0..511]
// Sync: per-part counters. "all part p finished step s" <=> c_p >= 32*(s+1).
//  part0 start t: c0 >= 32t        (own lockstep; h0 buffer)  c1 >= 32(t-1) (part1 read h0(t-2))
//  part1 start t: c1 >= 32t        c0 >= 32(t+1) (h0(t) ready) c2 >= 32(t-1) (gx1 buffer)
//  part2 start t: c2 >= 32t        c1 >= 32(t+1) (gx1(t) ready)
#define WHI_LD 1032
#define AS_LD 72                 // packed: hi[0..31] | lo[32..63] | pad
#define BLO_LD 40
#define SACC_LD 36
#define KCH 32
#define NCH 32
#define SMEM_WHI_BYTES (96 * WHI_LD * 2)            // 198144
#define STAGE_BUF_ELEMS (64 * AS_LD + 96 * BLO_LD)  // 8448 bf16
#define STAGE_BUF_BYTES (STAGE_BUF_ELEMS * 2)       // 16896
#define SMEM_UNION_BYTES (2 * STAGE_BUF_BYTES)      // 33792 (> sacc 27648)
#define SMEM_TOTAL_BYTES (SMEM_WHI_BYTES + SMEM_UNION_BYTES)  // 231936

__global__ void __launch_bounds__(NTHR) recur_kernel(
    const float* __restrict__ bx0, const float* __restrict__ bh0,
    const float* __restrict__ bx1, const float* __restrict__ bh1)
{
    extern __shared__ __align__(16) unsigned char s_raw[];
    __nv_bfloat16* Whi_s  = (__nv_bfloat16*)s_raw;
    __nv_bfloat16* stage0 = (__nv_bfloat16*)(s_raw + SMEM_WHI_BYTES);
    float*         saccf  = (float*)(s_raw + SMEM_WHI_BYTES);   // union with staging

    const int tid  = threadIdx.x;
    const int wid  = tid >> 5;
    const int part = blockIdx.x >> 5;           // 0..2
    const int j0   = (blockIdx.x & 31) * 32;
    const int g    = wid >> 2;                  // gate 0..2
    const int ms   = wid & 3;                   // A row slice 0..3

    const int widx = part + 1;                  // 1=Wh0, 2=Wx1, 3=Wh1

    // ---- stationary W_hi tile ----
    {
        const uint4* src = (const uint4*)(g_Whi[widx]);
        for (int l = tid; l < 96 * 128; l += NTHR) {
            int r = l >> 7, c = l & 127;
            int grow = (r >> 5) * 1024 + j0 + (r & 31);
            *(uint4*)&Whi_s[r * WHI_LD + c * 8] = src[grow * 128 + c];
        }
    }
    __syncthreads();

    const uint4* wlo_src = (const uint4*)(g_Wlo[widx]);
    const float* bx = (part == 0) ? bx0 : bx1;
    const float* bh = (part == 0) ? bh0 : bh1;

    const unsigned stage_u32 = (unsigned)__cvta_generic_to_shared(stage0);

    volatile unsigned* c0 = &g_cnt[0].v;
    volatile unsigned* c1 = &g_cnt[1].v;
    volatile unsigned* c2 = &g_cnt[2].v;

    for (int t = 0; t < TT; ++t) {
        // ---- dependency wait (thread 0 polls, block released by barrier) ----
        if (tid == 0) {
            int w_own, w_a = -1, w_b = -1;
            volatile unsigned *p_own, *p_a = 0, *p_b = 0;
            if (part == 0) { p_own = c0; w_own = 32 * t; p_a = c1; w_a = 32 * (t - 1); }
            else if (part == 1) { p_own = c1; w_own = 32 * t; p_a = c0; w_a = 32 * (t + 1); p_b = c2; w_b = 32 * (t - 1); }
            else { p_own = c2; w_own = 32 * t; p_a = c1; w_a = 32 * (t + 1); }
            if (w_own > 0) while ((int)*p_own < w_own) { }
            if (p_a && w_a > 0) while ((int)*p_a < w_a) { }
            if (p_b && w_b > 0) while ((int)*p_b < w_b) { }
            __threadfence();
        }
        __syncthreads();

        const __nv_bfloat16 *Ahi, *Alo;
        if (part == 0)      { Ahi = g_h0hi[(t + 1) & 1]; Alo = g_h0lo[(t + 1) & 1]; }
        else if (part == 1) { Ahi = g_h0hi[t & 1];       Alo = g_h0lo[t & 1]; }
        else                { Ahi = g_h1hi[(t + 1) & 1]; Alo = g_h1lo[(t + 1) & 1]; }

        const uint4* a_hi4 = (const uint4*)Ahi;
        const uint4* a_lo4 = (const uint4*)Alo;

        wmma::fragment<wmma::accumulator, 16, 16, 16, float> acc[2];
        wmma::fill_fragment(acc[0], 0.0f);
        wmma::fill_fragment(acc[1], 0.0f);

        // ---- staging: chunk c into buffer (c&1) ----
        auto stage = [&](int c) {
            const int kq = c * (KCH / 8);
            const unsigned buf = stage_u32 + (unsigned)((c & 1) * STAGE_BUF_BYTES);
            // A: 512 x 16B copies (hi|lo packed rows)
            {
                int l = tid;
                {
                    int r = l >> 3, s = l & 7;
                    const uint4* sp = (s < 4) ? (a_hi4 + r * 128 + kq + s)
                                              : (a_lo4 + r * 128 + kq + (s - 4));
                    int col = (s < 4) ? (s * 8) : (32 + (s - 4) * 8);
                    CP_ASYNC16(buf + (unsigned)((r * AS_LD + col) * 2), (const void*)sp);
                }
                if (l < 128) {
                    l += NTHR;
                    int r = l >> 3, s = l & 7;
                    const uint4* sp = (s < 4) ? (a_hi4 + r * 128 + kq + s)
                                              : (a_lo4 + r * 128 + kq + (s - 4));
                    int col = (s < 4) ? (s * 8) : (32 + (s - 4) * 8);
                    CP_ASYNC16(buf + (unsigned)((r * AS_LD + col) * 2), (const void*)sp);
                }
            }
            // Wlo: 384 copies, exactly 1 per thread
            {
                int r = tid >> 2, q = tid & 3;
                int grow = (r >> 5) * 1024 + j0 + (r & 31);
                unsigned d = buf + (unsigned)((64 * AS_LD + r * BLO_LD + q * 8) * 2);
                CP_ASYNC16(d, (const void*)(wlo_src + grow * 128 + kq + q));
            }
            CP_COMMIT();
        };

        stage(0);

        for (int c = 0; c < NCH; ++c) {
            CP_WAIT0();
            __syncthreads();
            if (c + 1 < NCH) stage(c + 1);

            const __nv_bfloat16* As  = stage0 + (c & 1) * STAGE_BUF_ELEMS;
            const __nv_bfloat16* Bls = As + 64 * AS_LD;
#pragma unroll
            for (int kk = 0; kk < KCH; kk += 16) {
                wmma::fragment<wmma::matrix_a, 16, 16, 16, __nv_bfloat16, wmma::row_major> ahi, alo;
                wmma::load_matrix_sync(ahi, As + ms * 16 * AS_LD + kk, AS_LD);
                wmma::load_matrix_sync(alo, As + ms * 16 * AS_LD + 32 + kk, AS_LD);
#pragma unroll
                for (int nf2 = 0; nf2 < 2; nf2++) {
                    wmma::fragment<wmma::matrix_b, 16, 16, 16, __nv_bfloat16, wmma::col_major> bhi, blo;
                    wmma::load_matrix_sync(bhi, &Whi_s[(g * 32 + nf2 * 16) * WHI_LD + c * KCH + kk], WHI_LD);
                    wmma::load_matrix_sync(blo, Bls + (g * 32 + nf2 * 16) * BLO_LD + kk, BLO_LD);
                    wmma::mma_sync(acc[nf2], ahi, bhi, acc[nf2]);
                    wmma::mma_sync(acc[nf2], ahi, blo, acc[nf2]);
                    wmma::mma_sync(acc[nf2], alo, bhi, acc[nf2]);
                }
            }
        }
        __syncthreads();   // staging reads done -> safe to write sacc (union)
#pragma unroll
        for (int nf2 = 0; nf2 < 2; nf2++)
            wmma::store_matrix_sync(saccf + (g * 64 + ms * 16) * SACC_LD + nf2 * 16,
                                    acc[nf2], SACC_LD, wmma::mem_row_major);
        __syncthreads();

        if (part == 1) {
            float* dst = g_gx1[t & 1];
            for (int l = tid; l < 64 * 32; l += NTHR) {
                int b = l >> 5, jj = l & 31;
                int j = j0 + jj;
                dst[b * G3 + j]        = saccf[(0 * 64 + b) * SACC_LD + jj];
                dst[b * G3 + 1024 + j] = saccf[(1 * 64 + b) * SACC_LD + jj];
                dst[b * G3 + 2048 + j] = saccf[(2 * 64 + b) * SACC_LD + jj];
            }
        } else {
            __nv_bfloat16* outhi = (part == 0) ? g_h0hi[t & 1] : g_h1hi[t & 1];
            __nv_bfloat16* outlo = (part == 0) ? g_h0lo[t & 1] : g_h1lo[t & 1];
            for (int l = tid; l < 64 * 32; l += NTHR) {
                int b = l >> 5, jj = l & 31;
                int j = j0 + jj;
                float ir, iz, in_;
                if (part == 0) {
                    const float* gxr = g_GX0 + (size_t)(t * BB + b) * G3;
                    ir  = __ldcg(&gxr[j])        + bx[j];
                    iz  = __ldcg(&gxr[1024 + j]) + bx[1024 + j];
                    in_ = __ldcg(&gxr[2048 + j]) + bx[2048 + j];
                } else {
                    const float* gxr = g_gx1[t & 1] + b * G3;
                    ir  = __ldcg(&gxr[j])        + bx[j];
                    iz  = __ldcg(&gxr[1024 + j]) + bx[1024 + j];
                    in_ = __ldcg(&gxr[2048 + j]) + bx[2048 + j];
                }
                float hr = saccf[(0 * 64 + b) * SACC_LD + jj] + bh[j];
                float hz = saccf[(1 * 64 + b) * SACC_LD + jj] + bh[1024 + j];
                float hn = saccf[(2 * 64 + b) * SACC_LD + jj] + bh[2048 + j];

                float r = fsig(ir + hr);
                float z = fsig(iz + hz);
                float n = ftanh(in_ + r * hn);
                float hp = ld_bf16_cg(&Ahi[b * HH + j]) + ld_bf16_cg(&Alo[b * HH + j]);
                float hnew = n + z * (hp - n);

                __nv_bfloat16 hh = __float2bfloat16(hnew);
                outhi[b * HH + j] = hh;
                outlo[b * HH + j] = __float2bfloat16(hnew - __bfloat162float(hh));
            }
        }

        // ---- signal completion of step t ----
        __syncthreads();
        if (tid == 0) {
            __threadfence();
            atomicAdd((unsigned*)&g_cnt[part].v, 1u);
        }
    }
}

// ---------------- FC: out[b] = h1(511)[b,:] . fcW + fcb ----------------
__global__ void fc_kernel(const float* __restrict__ fcW, const float* __restrict__ fcb,
                          float* __restrict__ out) {
    const int b = blockIdx.x;
    const int tid = threadIdx.x;
    const __nv_bfloat16* hh = g_h1hi[1] + b * HH;   // t=511 -> buffer 1
    const __nv_bfloat16* hl = g_h1lo[1] + b * HH;
    float s = 0.0f;
    for (int k = tid; k < HH; k += 128)
        s += (ld_bf16_cg(&hh[k]) + ld_bf16_cg(&hl[k])) * fcW[k];
    __shared__ float red[128];
    red[tid] = s;
    __syncthreads();
    for (int o = 64; o > 0; o >>= 1) {
        if (tid < o) red[tid] += red[tid + o];
        __syncthreads();
    }
    if (tid == 0) out[b] = red[0] + fcb[0];
}

// ---------------- host ----------------
extern "C" void kernel_launch(void* const* d_in, const int* in_sizes, int n_in,
                              void* d_out, int out_size) {
    const float* x   = (const float*)d_in[0];
    const float* Wx0 = (const float*)d_in[1];
    const float* bx0 = (const float*)d_in[2];
    const float* Wh0 = (const float*)d_in[3];
    const float* bh0 = (const float*)d_in[4];
    const float* Wx1 = (const float*)d_in[5];
    const float* bx1 = (const float*)d_in[6];
    const float* Wh1 = (const float*)d_in[7];
    const float* bh1 = (const float*)d_in[8];
    const float* fcW = (const float*)d_in[9];
    const float* fcb = (const float*)d_in[10];
    float* out = (float*)d_out;

    static int smem_set = 0;
    if (!smem_set) {
        cudaFuncSetAttribute(recur_kernel, cudaFuncAttributeMaxDynamicSharedMemorySize,
                             SMEM_TOTAL_BYTES);
        smem_set = 1;
    }

    // launch #0: fused splits + state init + counter reset
    setup_kernel<<<4096, 256>>>(Wx0, Wh0, Wx1, Wh1, x);

    // launch #1: parallel x-projection for layer 0
    {
        dim3 grid(G3 / 128, (TT * BB) / 128);   // (24, 256)
        phaseA_kernel<<<grid, 256>>>();
    }

    // launch #2: pad (keeps recur at process launch #5 for ncu -s 5)
    pad_kernel<<<1, 32>>>();

    // launch #3: persistent decoupled recurrence (512 steps per part)
    recur_kernel<<<NBLK, NTHR, SMEM_TOTAL_BYTES>>>(bx0, bh0, bx1, bh1);

    // launch #4: final FC
    fc_kernel<<<BB, 128>>>(fcW, fcb, out);

    (void)in_sizes; (void)n_in; (void)out_size;
}